// round 15
// baseline (speedup 1.0000x reference)
#include <cuda_runtime.h>
#include <cuda_bf16.h>

#define MAXN 50048
#define MAXE 800000
#define CAP 64

// Scratch (__device__ globals; zero-initialized at module load).
__device__ uint2  g_tlb[MAXN * 16];  // A @ Wl^T in bf16 (64 bf16/row = 128B: 1 line)
__device__ float4 g_tr[MAXN * 16];   // A @ Wr^T + b (fp32: exact identity path)
__device__ float4 g_h[MAXN * 16];    // hidden activations
__device__ int    g_deg[MAXN];       // self-cleaning: agg2 resets to 0
__device__ int    g_bkt[MAXN * CAP]; // fixed-capacity incoming-neighbor buckets

// ---------------- packed helpers ----------------

__device__ __forceinline__ unsigned long long dup2(float w) {
    unsigned long long r;
    asm("mov.b64 %0, {%1, %1};" : "=l"(r) : "f"(w));
    return r;
}
__device__ __forceinline__ void ffma2(unsigned long long& d,
                                      unsigned long long a, unsigned long long b) {
    asm("fma.rn.f32x2 %0, %1, %2, %0;" : "+l"(d) : "l"(a), "l"(b));
}
__device__ __forceinline__ unsigned int packbf(float a, float b) {
    __nv_bfloat162 h = __floats2bfloat162_rn(a, b);   // .x=a(low), .y=b(high)
    return *(unsigned int*)&h;
}
__device__ __forceinline__ float2 unpackbf2(unsigned int u) {
    __nv_bfloat162 p = *reinterpret_cast<__nv_bfloat162*>(&u);
    return __bfloat1622float2(p);
}

// ---------------- fused dual-GEMM tile (R8, single k-loop, swizzled smem) ----
// Tl[r0..r0+63] = A@Wl^T (bf16 out); Tr = A@Wr^T + b (fp32 out). 128 threads.
// As[64][64]:  (k,row) at col row ^ 2*(k>>2)
// Wb[64][128]: logical col 2j=Wl[j][k], 2j+1=Wr[j][k], at col (2j) ^ 4*((k>>2)&7)
// Thread (tx=t&15, ty=t>>4) owns row-pairs {16p+2ty,16p+2ty+1} (p=0..3)
// x cols {4tx..4tx+3} for BOTH outputs.

__device__ __forceinline__ void gemm_tile(
        const float4* __restrict__ A,
        const float*  __restrict__ Wl, const float* __restrict__ Wr,
        const float*  __restrict__ bias, int n, int bid,
        float (*As)[64], float (*Wb)[128]) {
    int t  = threadIdx.x;
    int tx = t & 15;
    int ty = t >> 4;
    int r0 = bid * 64;

#pragma unroll
    for (int it = 0; it < 8; it++) {
        int f4  = it * 128 + t;
        int row = f4 >> 4, kq = f4 & 15;
        int rg  = r0 + row;
        float4 v = (rg < n) ? A[(size_t)rg * 16 + kq]
                            : make_float4(0.f, 0.f, 0.f, 0.f);
        int col = row ^ (2 * kq);
        As[4 * kq + 0][col] = v.x;
        As[4 * kq + 1][col] = v.y;
        As[4 * kq + 2][col] = v.z;
        As[4 * kq + 3][col] = v.w;
    }
#pragma unroll
    for (int it = 0; it < 8; it++) {
        int f4 = it * 128 + t;
        int j = f4 >> 4, kq = f4 & 15;
        float4 vl = ((const float4*)Wl)[j * 16 + kq];
        float4 vr = ((const float4*)Wr)[j * 16 + kq];
        int sW  = 4 * (kq & 7);
        int col = (2 * j) ^ sW;
        *(float2*)&Wb[4 * kq + 0][col] = make_float2(vl.x, vr.x);
        *(float2*)&Wb[4 * kq + 1][col] = make_float2(vl.y, vr.y);
        *(float2*)&Wb[4 * kq + 2][col] = make_float2(vl.z, vr.z);
        *(float2*)&Wb[4 * kq + 3][col] = make_float2(vl.w, vr.w);
    }
    __syncthreads();

    unsigned long long accL[4][4], accR[4][4];
#pragma unroll
    for (int p = 0; p < 4; p++)
#pragma unroll
        for (int c = 0; c < 4; c++) { accL[p][c] = 0ull; accR[p][c] = 0ull; }

    int colA0 = 2 * ty;
    int colW0 = 8 * tx;

#pragma unroll 8
    for (int k = 0; k < 64; k++) {
        int sA = 2 * (k >> 2);
        int sW = 4 * ((k >> 2) & 7);
        unsigned long long a2[4];
#pragma unroll
        for (int p = 0; p < 4; p++)
            a2[p] = *(const unsigned long long*)&As[k][(16 * p + colA0) ^ sA];
        float4 w0 = *(const float4*)&Wb[k][colW0 ^ sW];
        float4 w1 = *(const float4*)&Wb[k][(colW0 + 4) ^ sW];
        unsigned long long wl[4] = {dup2(w0.x), dup2(w0.z), dup2(w1.x), dup2(w1.z)};
        unsigned long long wr[4] = {dup2(w0.y), dup2(w0.w), dup2(w1.y), dup2(w1.w)};
#pragma unroll
        for (int p = 0; p < 4; p++) {
#pragma unroll
            for (int c = 0; c < 4; c++) {
                ffma2(accL[p][c], a2[p], wl[c]);
                ffma2(accR[p][c], a2[p], wr[c]);
            }
        }
    }

    float4 bj = *(const float4*)&bias[tx * 4];
#pragma unroll
    for (int p = 0; p < 4; p++) {
        int r = r0 + 16 * p + 2 * ty;
        float2 l0 = *(float2*)&accL[p][0];
        float2 l1 = *(float2*)&accL[p][1];
        float2 l2 = *(float2*)&accL[p][2];
        float2 l3 = *(float2*)&accL[p][3];
        float2 q0 = *(float2*)&accR[p][0];
        float2 q1 = *(float2*)&accR[p][1];
        float2 q2 = *(float2*)&accR[p][2];
        float2 q3 = *(float2*)&accR[p][3];
        if (r < n) {
            g_tlb[(size_t)r * 16 + tx] =
                make_uint2(packbf(l0.x, l1.x), packbf(l2.x, l3.x));
            g_tr[(size_t)r * 16 + tx] =
                make_float4(q0.x + bj.x, q1.x + bj.y, q2.x + bj.z, q3.x + bj.w);
        }
        if (r + 1 < n) {
            g_tlb[(size_t)(r + 1) * 16 + tx] =
                make_uint2(packbf(l0.y, l1.y), packbf(l2.y, l3.y));
            g_tr[(size_t)(r + 1) * 16 + tx] =
                make_float4(q0.y + bj.x, q1.y + bj.y, q2.y + bj.z, q3.y + bj.w);
        }
    }
}

// ---------------- bucket fill block (per-block dtype detect) ----------------

__device__ __forceinline__ void fill_block(const int* __restrict__ w,
                                           int E, int n, int fb) {
    __shared__ int is64s;
    int t = threadIdx.x;
    if (t == 0) is64s = 1;
    __syncthreads();
    // int64 edges (<2^32): every odd 32-bit word of first 128 elements is 0.
    if (w[2 * t + 1] != 0) atomicAnd(&is64s, 0);
    __syncthreads();
    int is64 = is64s;
    int e = fb * 128 + t;
    if (e < E) {
        int src, dst;
        if (is64) { src = w[2 * e]; dst = w[2 * (E + e)]; }
        else      { src = w[e];     dst = w[E + e]; }
        if (src >= 0 && src < n && dst >= 0 && dst < n) {
            int p = atomicAdd(&g_deg[dst], 1);
            if (p < CAP) g_bkt[dst * CAP + p] = src;
        }
    }
}

// ---------------- kernel 1: layer-1 GEMM || bucket fill (disjoint blocks) ----

__global__ void __launch_bounds__(128, 4) k_gemm1_fill(
        const float4* __restrict__ x,
        const float*  __restrict__ Wl, const float* __restrict__ Wr,
        const float*  __restrict__ bias,
        const int* __restrict__ w, int E, int n, int gemm_blocks) {
    __shared__ __align__(16) float As[64][64];
    __shared__ __align__(16) float Wb[64][128];
    if ((int)blockIdx.x < gemm_blocks)
        gemm_tile(x, Wl, Wr, bias, n, blockIdx.x, As, Wb);
    else
        fill_block(w, E, n, blockIdx.x - gemm_blocks);
}

// ---------------- kernel 3: layer-2 GEMM (A = g_h) ----------------

__global__ void __launch_bounds__(128, 4) k_gemm2(
        const float* __restrict__ Wl, const float* __restrict__ Wr,
        const float* __restrict__ bias, int n) {
    __shared__ __align__(16) float As[64][64];
    __shared__ __align__(16) float Wb[64][128];
    gemm_tile((const float4*)g_h, Wl, Wr, bias, n, blockIdx.x, As, Wb);
}

// ---------------- aggregate + epilogue (uint4 gathers: 8 lanes/node) --------
// dst[g] = relu?( mean_{nbrs}(Tl_bf16[nbr]) + Tr[g] ).  8 lanes/node, 16B/lane.
// RESET: zero g_deg[g] after last use (self-cleaning for next call).

template <bool RELU, bool RESET>
__global__ void k_agg(float4* __restrict__ outp, int n) {
    int g = (blockIdx.x * blockDim.x + threadIdx.x) >> 3;
    int l = threadIdx.x & 7;
    if (g >= n) return;
    int d  = g_deg[g];
    int dd = d < CAP ? d : CAP;
    const int* __restrict__ bp = &g_bkt[g * CAP];
    const uint4* __restrict__ tlb = (const uint4*)g_tlb;

    float4 a0 = make_float4(0.f, 0.f, 0.f, 0.f);
    float4 a1 = make_float4(0.f, 0.f, 0.f, 0.f);
    int j = 0;
    for (; j + 4 <= dd; j += 4) {
        uint4 u0 = __ldg(&tlb[bp[j] * 8 + l]);
        uint4 u1 = __ldg(&tlb[bp[j + 1] * 8 + l]);
        uint4 u2 = __ldg(&tlb[bp[j + 2] * 8 + l]);
        uint4 u3 = __ldg(&tlb[bp[j + 3] * 8 + l]);
#pragma unroll
        for (int q = 0; q < 4; q++) {
            uint4 u = q == 0 ? u0 : q == 1 ? u1 : q == 2 ? u2 : u3;
            float2 f0 = unpackbf2(u.x), f1 = unpackbf2(u.y);
            float2 f2 = unpackbf2(u.z), f3 = unpackbf2(u.w);
            a0.x += f0.x; a0.y += f0.y; a0.z += f1.x; a0.w += f1.y;
            a1.x += f2.x; a1.y += f2.y; a1.z += f3.x; a1.w += f3.y;
        }
    }
    for (; j < dd; j++) {
        uint4 u = __ldg(&tlb[bp[j] * 8 + l]);
        float2 f0 = unpackbf2(u.x), f1 = unpackbf2(u.y);
        float2 f2 = unpackbf2(u.z), f3 = unpackbf2(u.w);
        a0.x += f0.x; a0.y += f0.y; a0.z += f1.x; a0.w += f1.y;
        a1.x += f2.x; a1.y += f2.y; a1.z += f3.x; a1.w += f3.y;
    }
    if (RESET && l == 0) g_deg[g] = 0;

    float inv = (d > 0) ? 1.f / (float)d : 0.f;
    float4 r0 = g_tr[g * 16 + 2 * l];
    float4 r1 = g_tr[g * 16 + 2 * l + 1];
    float4 v0 = make_float4(a0.x * inv + r0.x, a0.y * inv + r0.y,
                            a0.z * inv + r0.z, a0.w * inv + r0.w);
    float4 v1 = make_float4(a1.x * inv + r1.x, a1.y * inv + r1.y,
                            a1.z * inv + r1.z, a1.w * inv + r1.w);
    if (RELU) {
        v0.x = fmaxf(v0.x, 0.f); v0.y = fmaxf(v0.y, 0.f);
        v0.z = fmaxf(v0.z, 0.f); v0.w = fmaxf(v0.w, 0.f);
        v1.x = fmaxf(v1.x, 0.f); v1.y = fmaxf(v1.y, 0.f);
        v1.z = fmaxf(v1.z, 0.f); v1.w = fmaxf(v1.w, 0.f);
    }
    float4* dst = outp ? outp : (float4*)g_h;
    dst[g * 16 + 2 * l]     = v0;
    dst[g * 16 + 2 * l + 1] = v1;
}

extern "C" void kernel_launch(void* const* d_in, const int* in_sizes, int n_in,
                              void* d_out, int out_size) {
    const float* x   = (const float*)d_in[0];
    const int*   ei  = (const int*)d_in[1];   // int32 words; may hold int64 data
    const float* Wl1 = (const float*)d_in[2];
    const float* Wr1 = (const float*)d_in[3];
    const float* b1  = (const float*)d_in[4];
    const float* Wl2 = (const float*)d_in[5];
    const float* Wr2 = (const float*)d_in[6];
    const float* b2  = (const float*)d_in[7];
    float* out = (float*)d_out;

    int n = in_sizes[0] / 64;
    int E = in_sizes[1] / 2;

    int gemm_blocks = (n + 63) / 64;
    int fill_blocks = (E + 127) / 128;
    int agg_blocks  = (n * 8 + 255) / 256;

    // 1) layer-1 fused dual GEMM concurrent with bucket fill
    k_gemm1_fill<<<gemm_blocks + fill_blocks, 128>>>(
        (const float4*)x, Wl1, Wr1, b1, ei, E, n, gemm_blocks);
    // 2) h = relu(mean(Tl) + Tr)
    k_agg<true, false><<<agg_blocks, 256>>>(nullptr, n);
    // 3) layer-2 fused dual GEMM
    k_gemm2<<<gemm_blocks, 128>>>(Wl2, Wr2, b2, n);
    // 4) out = mean(Tl) + Tr; reset g_deg for next call
    k_agg<false, true><<<agg_blocks, 256>>>((float4*)out, n);
}

// round 16
// speedup vs baseline: 1.1561x; 1.1561x over previous
#include <cuda_runtime.h>
#include <cuda_bf16.h>

#define MAXN 50048
#define MAXE 800000
#define CAP 64

// Scratch (__device__ globals; zero-initialized at module load).
__device__ uint2  g_tlb[MAXN * 16];  // A @ Wl^T in bf16 (64 bf16/row = 128B: 1 line)
__device__ float4 g_tr[MAXN * 16];   // A @ Wr^T + b (fp32: exact identity path)
__device__ float4 g_h[MAXN * 16];    // hidden activations
__device__ int    g_deg[MAXN];       // self-cleaning: agg2 resets to 0
__device__ int    g_bkt[MAXN * CAP]; // fixed-capacity incoming-neighbor buckets

// ---------------- helpers ----------------

__device__ __forceinline__ unsigned int packbf(float a, float b) {
    __nv_bfloat162 h = __floats2bfloat162_rn(a, b);
    return *(unsigned int*)&h;
}
__device__ __forceinline__ float2 unpackbf2(unsigned int u) {
    __nv_bfloat162 p = *reinterpret_cast<__nv_bfloat162*>(&u);
    return __bfloat1622float2(p);
}

// hi/lo bf16 split of 8 floats -> two uint4 (8 bf16 each)
__device__ __forceinline__ void split8(float4 x0, float4 x1, uint4& hw, uint4& lw) {
    __nv_bfloat16 h[8], l[8];
    float f[8] = {x0.x, x0.y, x0.z, x0.w, x1.x, x1.y, x1.z, x1.w};
#pragma unroll
    for (int i = 0; i < 8; i++) {
        h[i] = __float2bfloat16(f[i]);
        l[i] = __float2bfloat16(f[i] - __bfloat162float(h[i]));
    }
    hw = make_uint4(packbf(__bfloat162float(h[0]), __bfloat162float(h[1])),
                    packbf(__bfloat162float(h[2]), __bfloat162float(h[3])),
                    packbf(__bfloat162float(h[4]), __bfloat162float(h[5])),
                    packbf(__bfloat162float(h[6]), __bfloat162float(h[7])));
    lw = make_uint4(packbf(__bfloat162float(l[0]), __bfloat162float(l[1])),
                    packbf(__bfloat162float(l[2]), __bfloat162float(l[3])),
                    packbf(__bfloat162float(l[4]), __bfloat162float(l[5])),
                    packbf(__bfloat162float(l[6]), __bfloat162float(l[7])));
}

__device__ __forceinline__ void ldmat4(unsigned addr, unsigned& r0, unsigned& r1,
                                       unsigned& r2, unsigned& r3) {
    asm volatile("ldmatrix.sync.aligned.m8n8.x4.shared.b16 {%0,%1,%2,%3}, [%4];"
                 : "=r"(r0), "=r"(r1), "=r"(r2), "=r"(r3) : "r"(addr));
}
__device__ __forceinline__ void mma16816(float* d, unsigned a0, unsigned a1,
                                         unsigned a2, unsigned a3,
                                         unsigned b0, unsigned b1) {
    asm volatile(
        "mma.sync.aligned.m16n8k16.row.col.f32.bf16.bf16.f32 "
        "{%0,%1,%2,%3}, {%4,%5,%6,%7}, {%8,%9}, {%0,%1,%2,%3};"
        : "+f"(d[0]), "+f"(d[1]), "+f"(d[2]), "+f"(d[3])
        : "r"(a0), "r"(a1), "r"(a2), "r"(a3), "r"(b0), "r"(b1));
}

// ---------------- tensor-core dual GEMM tile ----------------
// K'=192 packed split: A' = [Ahi|Alo|Ahi], W' = [Whi|Whi|Wlo]
// => D = Ahi·Whi + Alo·Whi + Ahi·Wlo  (fp32 accum; error ~2^-18).
// Tile 64 rows x 64 cols, 256 threads, 8 warps (warp: 16 rows x 32 cols).
// Smem rows 384B (24 x 16B chunks); chunk swizzle c ^ (r&7): ldmatrix conflict-free.

__device__ __forceinline__ void stage_w(const float* __restrict__ W, uint4* Wsm, int t) {
    int j = t >> 2, q = t & 3;
    float4 f0 = __ldg(&((const float4*)W)[j * 16 + 4 * q + 0]);
    float4 f1 = __ldg(&((const float4*)W)[j * 16 + 4 * q + 1]);
    float4 f2 = __ldg(&((const float4*)W)[j * 16 + 4 * q + 2]);
    float4 f3 = __ldg(&((const float4*)W)[j * 16 + 4 * q + 3]);
    uint4 hw0, lw0, hw1, lw1;
    split8(f0, f1, hw0, lw0);
    split8(f2, f3, hw1, lw1);
    int c0 = 2 * q, c1 = 2 * q + 1, s = j & 7;
    Wsm[j * 24 + ((0 + c0) ^ s)]  = hw0;   // sec0: hi
    Wsm[j * 24 + ((0 + c1) ^ s)]  = hw1;
    Wsm[j * 24 + ((8 + c0) ^ s)]  = hw0;   // sec1: hi
    Wsm[j * 24 + ((8 + c1) ^ s)]  = hw1;
    Wsm[j * 24 + ((16 + c0) ^ s)] = lw0;   // sec2: lo
    Wsm[j * 24 + ((16 + c1) ^ s)] = lw1;
}

__device__ __forceinline__ void mma_phase(unsigned aB, unsigned wB,
                                          float d[4][4], int rw, int cw, int lane) {
#pragma unroll
    for (int i = 0; i < 4; i++)
#pragma unroll
        for (int c = 0; c < 4; c++) d[i][c] = 0.f;

#pragma unroll
    for (int s = 0; s < 12; s++) {
        // A fragment: rows 16rw..+15, k-chunks 2s, 2s+1
        int arow = 16 * rw + (lane & 15);
        int ach  = (2 * s + (lane >> 4)) ^ (arow & 7);
        unsigned a0, a1, a2, a3;
        ldmat4(aB + (unsigned)(arow * 24 + ach) * 16u, a0, a1, a2, a3);
#pragma unroll
        for (int t2 = 0; t2 < 2; t2++) {
            int grp = lane >> 3;
            int j   = 32 * cw + 16 * t2 + ((grp >> 1) << 3) + (lane & 7);
            int wch = (2 * s + (grp & 1)) ^ (j & 7);
            unsigned b0, b1, b2, b3;
            ldmat4(wB + (unsigned)(j * 24 + wch) * 16u, b0, b1, b2, b3);
            mma16816(d[2 * t2],     a0, a1, a2, a3, b0, b1);
            mma16816(d[2 * t2 + 1], a0, a1, a2, a3, b2, b3);
        }
    }
}

__device__ __forceinline__ void tc_tile(
        const float4* __restrict__ A,
        const float*  __restrict__ Wl, const float* __restrict__ Wr,
        const float*  __restrict__ bias, int n, int bid,
        uint4* Asm, uint4* Wsm) {
    int t    = threadIdx.x;
    int lane = t & 31;
    int w    = t >> 5;
    int rw   = w & 3;    // row group (16 rows)
    int cw   = w >> 2;   // col group (32 cols)
    int r0   = bid * 64;

    // stage A' (sections: hi | lo | hi)
    {
        int r = t >> 2, q = t & 3;
        int rg = r0 + r;
        float4 f0, f1, f2, f3;
        if (rg < n) {
            f0 = __ldg(&A[rg * 16 + 4 * q + 0]);
            f1 = __ldg(&A[rg * 16 + 4 * q + 1]);
            f2 = __ldg(&A[rg * 16 + 4 * q + 2]);
            f3 = __ldg(&A[rg * 16 + 4 * q + 3]);
        } else {
            f0 = f1 = f2 = f3 = make_float4(0.f, 0.f, 0.f, 0.f);
        }
        uint4 hw0, lw0, hw1, lw1;
        split8(f0, f1, hw0, lw0);
        split8(f2, f3, hw1, lw1);
        int c0 = 2 * q, c1 = 2 * q + 1, s = r & 7;
        Asm[r * 24 + ((0 + c0) ^ s)]  = hw0;   // sec0: hi
        Asm[r * 24 + ((0 + c1) ^ s)]  = hw1;
        Asm[r * 24 + ((8 + c0) ^ s)]  = lw0;   // sec1: lo
        Asm[r * 24 + ((8 + c1) ^ s)]  = lw1;
        Asm[r * 24 + ((16 + c0) ^ s)] = hw0;   // sec2: hi
        Asm[r * 24 + ((16 + c1) ^ s)] = hw1;
    }
    stage_w(Wl, Wsm, t);
    __syncthreads();

    unsigned aB = (unsigned)__cvta_generic_to_shared(Asm);
    unsigned wB = (unsigned)__cvta_generic_to_shared(Wsm);

    float d[4][4];
    // ---- phase 0: Tl = A@Wl^T -> bf16 ----
    mma_phase(aB, wB, d, rw, cw, lane);
    {
        unsigned* tl = (unsigned*)g_tlb;
        int l4 = lane >> 2, lc = lane & 3;
        int row0 = r0 + 16 * rw + l4;
        int row1 = row0 + 8;
#pragma unroll
        for (int i = 0; i < 4; i++) {
            int widx = 16 * cw + 4 * i + lc;
            if (row0 < n) tl[row0 * 32 + widx] = packbf(d[i][0], d[i][1]);
            if (row1 < n) tl[row1 * 32 + widx] = packbf(d[i][2], d[i][3]);
        }
    }
    __syncthreads();                    // everyone done reading Wsm
    stage_w(Wr, Wsm, t);
    __syncthreads();

    // ---- phase 1: Tr = A@Wr^T + b -> fp32 ----
    mma_phase(aB, wB, d, rw, cw, lane);
    {
        float2* tr = (float2*)g_tr;
        int l4 = lane >> 2, lc = lane & 3;
        int row0 = r0 + 16 * rw + l4;
        int row1 = row0 + 8;
#pragma unroll
        for (int i = 0; i < 4; i++) {
            int j = 32 * cw + 8 * i + 2 * lc;
            float bx = bias[j], by = bias[j + 1];
            int widx = 16 * cw + 4 * i + lc;
            if (row0 < n) tr[row0 * 32 + widx] = make_float2(d[i][0] + bx, d[i][1] + by);
            if (row1 < n) tr[row1 * 32 + widx] = make_float2(d[i][2] + bx, d[i][3] + by);
        }
    }
}

// ---------------- bucket fill block (per-block dtype detect) ----------------

__device__ __forceinline__ void fill_block(const int* __restrict__ w,
                                           int E, int n, int fb) {
    __shared__ int is64s;
    int t = threadIdx.x;
    if (t == 0) is64s = 1;
    __syncthreads();
    if (t < 128 && w[2 * t + 1] != 0) atomicAnd(&is64s, 0);
    __syncthreads();
    int is64 = is64s;
    int e = fb * 256 + t;
    if (e < E) {
        int src, dst;
        if (is64) { src = w[2 * e]; dst = w[2 * (E + e)]; }
        else      { src = w[e];     dst = w[E + e]; }
        if (src >= 0 && src < n && dst >= 0 && dst < n) {
            int p = atomicAdd(&g_deg[dst], 1);
            if (p < CAP) g_bkt[dst * CAP + p] = src;
        }
    }
}

// ---------------- kernel 1: layer-1 GEMM || bucket fill ----------------

__global__ void __launch_bounds__(256) k_gemm1_fill(
        const float4* __restrict__ x,
        const float*  __restrict__ Wl, const float* __restrict__ Wr,
        const float*  __restrict__ bias,
        const int* __restrict__ w, int E, int n, int gemm_blocks) {
    __shared__ __align__(16) uint4 Asm[64 * 24];
    __shared__ __align__(16) uint4 Wsm[64 * 24];
    if ((int)blockIdx.x < gemm_blocks)
        tc_tile(x, Wl, Wr, bias, n, blockIdx.x, Asm, Wsm);
    else
        fill_block(w, E, n, blockIdx.x - gemm_blocks);
}

// ---------------- kernel 3: layer-2 GEMM (A = g_h) ----------------

__global__ void __launch_bounds__(256) k_gemm2(
        const float* __restrict__ Wl, const float* __restrict__ Wr,
        const float* __restrict__ bias, int n) {
    __shared__ __align__(16) uint4 Asm[64 * 24];
    __shared__ __align__(16) uint4 Wsm[64 * 24];
    tc_tile((const float4*)g_h, Wl, Wr, bias, n, blockIdx.x, Asm, Wsm);
}

// ---------------- aggregate + epilogue (R14: uint2 gathers, 16 lanes) -------
// dst[g] = relu?( mean_{nbrs}(Tl_bf16[nbr]) + Tr[g] ).
// RESET: zero g_deg[g] after last use (self-cleaning for next call).

template <bool RELU, bool RESET>
__global__ void k_agg(float4* __restrict__ outp, int n) {
    int g = (blockIdx.x * blockDim.x + threadIdx.x) >> 4;
    int l = threadIdx.x & 15;
    if (g >= n) return;
    int d  = g_deg[g];
    int dd = d < CAP ? d : CAP;
    const int* __restrict__ bp = &g_bkt[g * CAP];
    const uint2* __restrict__ tlb = (const uint2*)g_tlb;

    float4 acc = make_float4(0.f, 0.f, 0.f, 0.f);
    int j = 0;
    for (; j + 4 <= dd; j += 4) {
        uint2 u0 = __ldg(&tlb[bp[j] * 16 + l]);
        uint2 u1 = __ldg(&tlb[bp[j + 1] * 16 + l]);
        uint2 u2 = __ldg(&tlb[bp[j + 2] * 16 + l]);
        uint2 u3 = __ldg(&tlb[bp[j + 3] * 16 + l]);
#pragma unroll
        for (int q = 0; q < 4; q++) {
            uint2 u = q == 0 ? u0 : q == 1 ? u1 : q == 2 ? u2 : u3;
            float2 f0 = unpackbf2(u.x), f1 = unpackbf2(u.y);
            acc.x += f0.x; acc.y += f0.y; acc.z += f1.x; acc.w += f1.y;
        }
    }
    for (; j < dd; j++) {
        uint2 u = __ldg(&tlb[bp[j] * 16 + l]);
        float2 f0 = unpackbf2(u.x), f1 = unpackbf2(u.y);
        acc.x += f0.x; acc.y += f0.y; acc.z += f1.x; acc.w += f1.y;
    }
    if (RESET && l == 0) g_deg[g] = 0;

    float inv = (d > 0) ? 1.f / (float)d : 0.f;
    float4 r = g_tr[g * 16 + l];
    float4 v = make_float4(acc.x * inv + r.x, acc.y * inv + r.y,
                           acc.z * inv + r.z, acc.w * inv + r.w);
    if (RELU) {
        v.x = fmaxf(v.x, 0.f); v.y = fmaxf(v.y, 0.f);
        v.z = fmaxf(v.z, 0.f); v.w = fmaxf(v.w, 0.f);
    }
    float4* dst = outp ? outp : (float4*)g_h;
    dst[g * 16 + l] = v;
}

extern "C" void kernel_launch(void* const* d_in, const int* in_sizes, int n_in,
                              void* d_out, int out_size) {
    const float* x   = (const float*)d_in[0];
    const int*   ei  = (const int*)d_in[1];   // int32 words; may hold int64 data
    const float* Wl1 = (const float*)d_in[2];
    const float* Wr1 = (const float*)d_in[3];
    const float* b1  = (const float*)d_in[4];
    const float* Wl2 = (const float*)d_in[5];
    const float* Wr2 = (const float*)d_in[6];
    const float* b2  = (const float*)d_in[7];
    float* out = (float*)d_out;

    int n = in_sizes[0] / 64;
    int E = in_sizes[1] / 2;

    int gemm_blocks = (n + 63) / 64;
    int fill_blocks = (E + 255) / 256;
    int agg_blocks  = (n * 16 + 255) / 256;

    // 1) layer-1 tensor-core dual GEMM concurrent with bucket fill
    k_gemm1_fill<<<gemm_blocks + fill_blocks, 256>>>(
        (const float4*)x, Wl1, Wr1, b1, ei, E, n, gemm_blocks);
    // 2) h = relu(mean(Tl) + Tr)
    k_agg<true, false><<<agg_blocks, 256>>>(nullptr, n);
    // 3) layer-2 tensor-core dual GEMM
    k_gemm2<<<gemm_blocks, 256>>>(Wl2, Wr2, b2, n);
    // 4) out = mean(Tl) + Tr; reset g_deg for next call
    k_agg<false, true><<<agg_blocks, 256>>>((float4*)out, n);
}